// round 10
// baseline (speedup 1.0000x reference)
#include <cuda_runtime.h>
#include <cstdint>

// Problem constants (from reference)
#define SEQ    4096
#define CIN    7
#define NK     586        // 585 regular kernels + 1 "last"
#define GLEN   12288      // SEQ * KW(3)
#define HP     12289      // output positions per channel-kernel row
#define GPITCH 12304      // GLEN + 16, keeps 16B alignment
#define CTOT   4096       // 7*585 + 1
#define NCP    2048       // c-pairs
#define GROUPS 74         // h-groups (one wave: 8 x 74 = 592 CTAs = 148 SM x 4)
#define RPG    168        // rows per group (74*168 = 12432 >= HP), multiple of 12

typedef unsigned long long u64;

// Scratch (allocation-free rule: __device__ globals). +16 slack u64s for window overreads.
__device__ u64   g_Gdup[CIN * GPITCH + 16]; // duplicated signal: (g,g) f32x2, g[i]=g_ch[i-4]
__device__ float g_Wmid[NK * 8];            // middle column of each 8x3 kernel (slow path)
__device__ u64   g_WpkT[8 * NCP];           // TRANSPOSED packed weights: [tap][cpair]

__device__ __forceinline__ u64 pk2(float lo, float hi) {
    u64 r; asm("mov.b64 %0, {%1,%2};" : "=l"(r) : "f"(lo), "f"(hi)); return r;
}
__device__ __forceinline__ u64 fma2(u64 a, u64 b, u64 c) {
    u64 d; asm("fma.rn.f32x2 %0, %1, %2, %3;" : "=l"(d) : "l"(a), "l"(b), "l"(c)); return d;
}
__device__ __forceinline__ float lo32(u64 v) { return __uint_as_float((unsigned)v); }
__device__ __forceinline__ float hi32(u64 v) { return __uint_as_float((unsigned)(v >> 32)); }

// ---- fused prep: mid-column weights, transposed packed weight pairs, duplicated signal ----
__global__ void prep(const float* __restrict__ x, const float* __restrict__ kernels) {
    int idx = blockIdx.x * blockDim.x + threadIdx.x;
    if (idx < NK * 8) {
        int k = idx >> 3, a = idx & 7;
        g_Wmid[idx] = kernels[k * 24 + a * 3 + 1];
    }
    if (idx < 8 * NCP) {
        int a = idx / NCP, cp = idx - a * NCP;
        int c0 = 2 * cp, c1 = c0 + 1;
        int k0 = (c0 == CTOT - 1) ? 585 : (c0 % 585);
        int k1 = (c1 == CTOT - 1) ? 585 : (c1 % 585);
        g_WpkT[idx] = pk2(kernels[k0 * 24 + a * 3 + 1], kernels[k1 * 24 + a * 3 + 1]);
    }
    if (idx < CIN * GPITCH) {
        int ch = idx / GPITCH;
        int i  = idx - ch * GPITCH;
        int t  = i - 4;
        float v = 0.f;
        if (t >= 0 && t < GLEN) {
            int s = t / 3;
            int j = t - s * 3;
            int src = s + j;
            if (src > SEQ - 1) src = SEQ - 1;
            v = x[src * CIN + ch];
        }
        g_Gdup[idx] = pk2(v, v);
    }
}

// One 2-row phase: ring indices are compile-time constants -> pure register renaming.
#define PHASE(p) do {                                                          \
    u64 acc0 = 0ull, acc1 = 0ull;                                              \
    _Pragma("unroll")                                                          \
    for (int a = 0; a < 8; a++) {                                              \
        acc0 = fma2(P[(2*(p)     + a) % 12], W[a], acc0);                      \
        acc1 = fma2(P[(2*(p) + 1 + a) % 12], W[a], acc1);                      \
    }                                                                          \
    *(u64*)op = acc0;  op += CTOT;                                             \
    *(u64*)op = acc1;  op += CTOT;                                             \
    {                                                                          \
        ulonglong2 nv = *(const ulonglong2*)(gp + base + 2*(p) + 10);          \
        P[(2*(p) + 10) % 12] = nv.x;                                           \
        P[(2*(p) + 11) % 12] = nv.y;                                           \
    }                                                                          \
} while (0)

// ---- main kernel: one-wave grid; each CTA sweeps a 168-row group for its 512 c ----
__global__ void __launch_bounds__(256, 4) conv_main(float* __restrict__ out) {
    const int tid = threadIdx.x;
    const int cp  = blockIdx.x * 256 + tid;     // [0, 2048), grid.x = 8
    const int c0  = cp * 2;
    const int r0  = blockIdx.y * RPG;           // group start row

    const int ch0 = c0 / 585;                   // c0 even -> never the special 4095
    const int c1  = c0 + 1;
    const int ch1 = (c1 == CTOT - 1) ? 0 : c1 / 585;
    const bool uniform = (ch0 == ch1);

    if (uniform) {
        // 8 packed weight pairs, warp-contiguous SoA loads — once per CTA
        u64 W[8];
#pragma unroll
        for (int a = 0; a < 8; a++) W[a] = g_WpkT[a * NCP + cp];

        const u64* __restrict__ gp = &g_Gdup[ch0 * GPITCH + r0];   // 16B-aligned (r0 even)

        // Ring init: relative offsets 0..9
        u64 P[12];
        {
            ulonglong2 t0 = *(const ulonglong2*)(gp);
            ulonglong2 t1 = *(const ulonglong2*)(gp + 2);
            ulonglong2 t2 = *(const ulonglong2*)(gp + 4);
            ulonglong2 t3 = *(const ulonglong2*)(gp + 6);
            ulonglong2 t4 = *(const ulonglong2*)(gp + 8);
            P[0] = t0.x; P[1] = t0.y; P[2] = t1.x; P[3] = t1.y;
            P[4] = t2.x; P[5] = t2.y; P[6] = t3.x; P[7] = t3.y;
            P[8] = t4.x; P[9] = t4.y; P[10] = 0;  P[11] = 0;
        }

        float* op = out + (size_t)r0 * CTOT + c0;
#pragma unroll 1
        for (int it = 0; it < RPG / 12; it++) {
            const int base = it * 12;
            if (r0 + base + 12 <= HP) {
                PHASE(0); PHASE(1); PHASE(2);
                PHASE(3); PHASE(4); PHASE(5);
            } else {
                // Tail: per-row scalar (at most 11 rows), then done with this group.
                for (int h = r0 + base; h < HP; h++) {
                    const float* ga = (const float*)(gp + (h - r0));  // dup pairs
                    float s0 = 0.f, s1 = 0.f;
#pragma unroll
                    for (int a = 0; a < 8; a++) {
                        float gv = ga[2 * a];
                        s0 = fmaf(gv, lo32(W[a]), s0);
                        s1 = fmaf(gv, hi32(W[a]), s1);
                    }
                    float2 o; o.x = s0; o.y = s1;
                    *(float2*)&out[(size_t)h * CTOT + c0] = o;
                }
                break;
            }
        }
    } else {
        // Slow path: 4 channel-crossing pairs of 2048 — scalar over the whole group.
        int kk0 = (c0 == CTOT - 1) ? 585 : c0 % 585;
        int kk1 = (c1 == CTOT - 1) ? 585 : c1 % 585;
        float w0[8], w1[8];
#pragma unroll
        for (int a = 0; a < 8; a++) {
            w0[a] = g_Wmid[kk0 * 8 + a];
            w1[a] = g_Wmid[kk1 * 8 + a];
        }
        int hEnd = min(r0 + RPG, HP);
        for (int h = r0; h < hEnd; h++) {
            const float* ga = (const float*)&g_Gdup[ch0 * GPITCH + h];
            const float* gb = (const float*)&g_Gdup[ch1 * GPITCH + h];
            float s0 = 0.f, s1 = 0.f;
#pragma unroll
            for (int a = 0; a < 8; a++) {
                s0 = fmaf(ga[2 * a], w0[a], s0);
                s1 = fmaf(gb[2 * a], w1[a], s1);
            }
            float2 o; o.x = s0; o.y = s1;
            *(float2*)&out[(size_t)h * CTOT + c0] = o;
        }
    }
}

extern "C" void kernel_launch(void* const* d_in, const int* in_sizes, int n_in,
                              void* d_out, int out_size) {
    const float* x       = (const float*)d_in[0];
    const float* kernels = (const float*)d_in[1];
    if (n_in >= 2 && in_sizes[0] == NK * 24) {   // defensive: swapped order
        kernels = (const float*)d_in[0];
        x       = (const float*)d_in[1];
    }
    float* out = (float*)d_out;

    prep<<<(CIN * GPITCH + 255) / 256, 256>>>(x, kernels);

    dim3 grid(NCP / 256, GROUPS);                // (8, 74) = 592 CTAs = one wave
    conv_main<<<grid, 256>>>(out);
}

// round 11
// speedup vs baseline: 1.0462x; 1.0462x over previous
#include <cuda_runtime.h>
#include <cstdint>

// Problem constants (from reference)
#define SEQ    4096
#define CIN    7
#define NK     586        // 585 regular kernels + 1 "last"
#define GLEN   12288      // SEQ * KW(3)
#define HP     12289      // output positions per channel-kernel row
#define GPITCH 12304      // GLEN + 16, keeps 16B alignment
#define CTOT   4096       // 7*585 + 1
#define NQ     1024       // c-quads
#define HTILE  16

typedef unsigned long long u64;

// Scratch (allocation-free rule: __device__ globals). +16 slack u64s for window overreads.
__device__ u64   g_Gdup[CIN * GPITCH + 16]; // duplicated signal: (g,g) f32x2, g[i]=g_ch[i-4]
__device__ float g_Wmid[NK * 8];            // middle column of each 8x3 kernel (slow path)
__device__ ulonglong2 g_WqT[8 * NQ];        // TRANSPOSED packed quad weights: [tap][quad]

__device__ __forceinline__ u64 pk2(float lo, float hi) {
    u64 r; asm("mov.b64 %0, {%1,%2};" : "=l"(r) : "f"(lo), "f"(hi)); return r;
}
__device__ __forceinline__ u64 fma2(u64 a, u64 b, u64 c) {
    u64 d; asm("fma.rn.f32x2 %0, %1, %2, %3;" : "=l"(d) : "l"(a), "l"(b), "l"(c)); return d;
}

// ---- fused prep: mid-column weights, transposed packed quad weights, duplicated signal ----
__global__ void prep(const float* __restrict__ x, const float* __restrict__ kernels) {
    int idx = blockIdx.x * blockDim.x + threadIdx.x;
    if (idx < NK * 8) {
        int k = idx >> 3, a = idx & 7;
        g_Wmid[idx] = kernels[k * 24 + a * 3 + 1];
    }
    if (idx < 8 * NQ) {
        int a = idx / NQ, q = idx - a * NQ;          // [tap][quad] layout
        float w[4];
#pragma unroll
        for (int j = 0; j < 4; j++) {
            int c = 4 * q + j;
            int k = (c == CTOT - 1) ? 585 : (c % 585);
            w[j] = kernels[k * 24 + a * 3 + 1];
        }
        ulonglong2 v; v.x = pk2(w[0], w[1]); v.y = pk2(w[2], w[3]);
        g_WqT[idx] = v;
    }
    if (idx < CIN * GPITCH) {
        int ch = idx / GPITCH;
        int i  = idx - ch * GPITCH;
        int t  = i - 4;
        float v = 0.f;
        if (t >= 0 && t < GLEN) {
            int s = t / 3;
            int j = t - s * 3;
            int src = s + j;
            if (src > SEQ - 1) src = SEQ - 1;
            v = x[src * CIN + ch];
        }
        g_Gdup[idx] = pk2(v, v);
    }
}

// ---- main kernel: one c-quad per thread, HTILE=16 rows, STG.128 per row,
//      SoA warp-contiguous weight loads, pre-duplicated g window, 3076 CTAs ----
__global__ void __launch_bounds__(256, 3) conv_main(float* __restrict__ out) {
    const int tid = threadIdx.x;
    const int q   = blockIdx.x * 256 + tid;     // [0, 1024), grid.x = 4
    const int c0  = q * 4;
    const int h0  = blockIdx.y * HTILE;

    const int ch0 = c0 / 585;
    const int c3  = c0 + 3;
    const int ch3 = (c3 == CTOT - 1) ? 0 : c3 / 585;

    const bool uniform  = (ch0 == ch3);
    const bool fulltile = (h0 + HTILE <= HP);

    if (uniform && fulltile) {
        // 8 taps x 2 packed weight pairs; SoA -> warp-contiguous 16B/thread loads
        u64 W0[8], W1[8];
#pragma unroll
        for (int a = 0; a < 8; a++) {
            ulonglong2 t = g_WqT[a * NQ + q];
            W0[a] = t.x; W1[a] = t.y;
        }

        const u64* __restrict__ gp = &g_Gdup[ch0 * GPITCH + h0];   // 16B-aligned

        // Sliding window of 12 duplicated values, LDG.128 broadcast loads
        u64 P[12];
        {
            ulonglong2 a0 = *(const ulonglong2*)(gp);
            ulonglong2 a1 = *(const ulonglong2*)(gp + 2);
            ulonglong2 a2 = *(const ulonglong2*)(gp + 4);
            ulonglong2 a3 = *(const ulonglong2*)(gp + 6);
            ulonglong2 a4 = *(const ulonglong2*)(gp + 8);
            ulonglong2 a5 = *(const ulonglong2*)(gp + 10);
            P[0] = a0.x; P[1] = a0.y; P[2]  = a1.x; P[3]  = a1.y;
            P[4] = a2.x; P[5] = a2.y; P[6]  = a3.x; P[7]  = a3.y;
            P[8] = a4.x; P[9] = a4.y; P[10] = a5.x; P[11] = a5.y;
        }

        char* op = (char*)(out + (size_t)h0 * CTOT + c0);
#pragma unroll
        for (int hb = 0; hb < HTILE; hb += 4) {
            ulonglong2 n0, n1;
            if (hb < HTILE - 4) {
                n0 = *(const ulonglong2*)(gp + hb + 12);
                n1 = *(const ulonglong2*)(gp + hb + 14);
            }
#pragma unroll
            for (int u = 0; u < 4; u++) {
                u64 a0 = 0ull, a1 = 0ull;
#pragma unroll
                for (int a = 0; a < 8; a++) {
                    u64 g2 = P[u + a];
                    a0 = fma2(g2, W0[a], a0);
                    a1 = fma2(g2, W1[a], a1);
                }
                ulonglong2 st; st.x = a0; st.y = a1;
                *(ulonglong2*)op = st;                  // STG.128: out[h][c0..c0+3]
                op += CTOT * sizeof(float);
            }
            if (hb < HTILE - 4) {
#pragma unroll
                for (int i = 0; i < 8; i++) P[i] = P[i + 4];
                P[8] = n0.x; P[9] = n0.y; P[10] = n1.x; P[11] = n1.y;
            }
        }
    } else {
        // Slow path: channel-crossing quads (7 of 1024) and the 1-row tail tile.
        int hEnd = min(h0 + HTILE, HP);
        int chv[4], kkv[4];
#pragma unroll
        for (int j = 0; j < 4; j++) {
            int c = c0 + j;
            if (c == CTOT - 1) { chv[j] = 0; kkv[j] = 585; }
            else               { chv[j] = c / 585; kkv[j] = c % 585; }
        }
        for (int h = h0; h < hEnd; h++) {
            float acc[4];
#pragma unroll
            for (int j = 0; j < 4; j++) {
                const float* gpj = (const float*)&g_Gdup[chv[j] * GPITCH + h];
                float s = 0.f;
#pragma unroll
                for (int a = 0; a < 8; a++) s = fmaf(gpj[2 * a], g_Wmid[kkv[j] * 8 + a], s);
                acc[j] = s;
            }
            float4 o; o.x = acc[0]; o.y = acc[1]; o.z = acc[2]; o.w = acc[3];
            *(float4*)&out[(size_t)h * CTOT + c0] = o;
        }
    }
}

extern "C" void kernel_launch(void* const* d_in, const int* in_sizes, int n_in,
                              void* d_out, int out_size) {
    const float* x       = (const float*)d_in[0];
    const float* kernels = (const float*)d_in[1];
    if (n_in >= 2 && in_sizes[0] == NK * 24) {   // defensive: swapped order
        kernels = (const float*)d_in[0];
        x       = (const float*)d_in[1];
    }
    float* out = (float*)d_out;

    prep<<<(CIN * GPITCH + 255) / 256, 256>>>(x, kernels);

    dim3 grid(NQ / 256, (HP + HTILE - 1) / HTILE);  // (4, 769) = 3076 CTAs
    conv_main<<<grid, 256>>>(out);
}

// round 12
// speedup vs baseline: 1.4148x; 1.3523x over previous
#include <cuda_runtime.h>
#include <cstdint>

// Problem constants (from reference)
#define SEQ    4096
#define CIN    7
#define NK     586        // 585 regular kernels + 1 "last"
#define GLEN   12288      // SEQ * KW(3)
#define HP     12289      // output positions per channel-kernel row
#define GPITCH 12304      // GLEN + 16, keeps 16B alignment
#define CTOT   4096       // 7*585 + 1
#define NCP    2048       // c-pairs
#define HTILE  36         // 3 ring cycles of 12 rows

typedef unsigned long long u64;

// Scratch (allocation-free rule: __device__ globals). +16 slack u64s for window overreads.
__device__ u64   g_Gdup[CIN * GPITCH + 16]; // duplicated signal: (g,g) f32x2, g[i]=g_ch[i-4]
__device__ float g_Wmid[NK * 8];            // middle column of each 8x3 kernel (slow path)
__device__ u64   g_WpkT[8 * NCP];           // TRANSPOSED packed weights: [tap][cpair]

__device__ __forceinline__ u64 pk2(float lo, float hi) {
    u64 r; asm("mov.b64 %0, {%1,%2};" : "=l"(r) : "f"(lo), "f"(hi)); return r;
}
__device__ __forceinline__ u64 fma2(u64 a, u64 b, u64 c) {
    u64 d; asm("fma.rn.f32x2 %0, %1, %2, %3;" : "=l"(d) : "l"(a), "l"(b), "l"(c)); return d;
}

// ---- fused prep: mid-column weights, transposed packed weight pairs, duplicated signal ----
__global__ void prep(const float* __restrict__ x, const float* __restrict__ kernels) {
    int idx = blockIdx.x * blockDim.x + threadIdx.x;
    if (idx < NK * 8) {
        int k = idx >> 3, a = idx & 7;
        g_Wmid[idx] = kernels[k * 24 + a * 3 + 1];
    }
    if (idx < 8 * NCP) {
        int a = idx / NCP, cp = idx - a * NCP;
        int c0 = 2 * cp, c1 = c0 + 1;
        int k0 = (c0 == CTOT - 1) ? 585 : (c0 % 585);
        int k1 = (c1 == CTOT - 1) ? 585 : (c1 % 585);
        g_WpkT[idx] = pk2(kernels[k0 * 24 + a * 3 + 1], kernels[k1 * 24 + a * 3 + 1]);
    }
    if (idx < CIN * GPITCH) {
        int ch = idx / GPITCH;
        int i  = idx - ch * GPITCH;
        int t  = i - 4;
        float v = 0.f;
        if (t >= 0 && t < GLEN) {
            int s = t / 3;
            int j = t - s * 3;
            int src = s + j;
            if (src > SEQ - 1) src = SEQ - 1;
            v = x[src * CIN + ch];
        }
        g_Gdup[idx] = pk2(v, v);
    }
}

// One 4-row phase: ring slots (4p+u+a)%12 are compile-time -> zero shift MOVs.
// After computing rows 4p..4p+3 (of this 12-row cycle), refill slots with the
// next 4 values via two LDG.128.
#define PHASE(p) do {                                                          \
    _Pragma("unroll")                                                          \
    for (int u = 0; u < 4; u++) {                                              \
        u64 acc = 0ull;                                                        \
        _Pragma("unroll")                                                      \
        for (int a = 0; a < 8; a++)                                            \
            acc = fma2(P[(4*(p) + u + a) % 12], W[a], acc);                    \
        *(u64*)op = acc;                                                       \
        op += CTOT * sizeof(float);                                            \
    }                                                                          \
    {                                                                          \
        ulonglong2 nv0 = *(const ulonglong2*)(gp + base + 4*(p) + 12);         \
        ulonglong2 nv1 = *(const ulonglong2*)(gp + base + 4*(p) + 14);         \
        P[(4*(p))     % 12] = nv0.x;                                           \
        P[(4*(p) + 1) % 12] = nv0.y;                                           \
        P[(4*(p) + 2) % 12] = nv1.x;                                           \
        P[(4*(p) + 3) % 12] = nv1.y;                                           \
    }                                                                          \
} while (0)

// ---- main kernel: one c-pair per thread, 36 rows per tile, STG.64 per row,
//      SoA weight loads, pre-duplicated g, mod-12 ring window (no shift MOVs) ----
__global__ void __launch_bounds__(256, 4) conv_main(float* __restrict__ out) {
    const int tid = threadIdx.x;
    const int cp  = blockIdx.x * 256 + tid;     // [0, 2048), grid.x = 8
    const int c0  = cp * 2;
    const int h0  = blockIdx.y * HTILE;

    const int ch0 = c0 / 585;                   // c0 even -> never the special 4095
    const int c1  = c0 + 1;
    const int ch1 = (c1 == CTOT - 1) ? 0 : c1 / 585;

    const bool uniform  = (ch0 == ch1);
    const bool fulltile = (h0 + HTILE <= HP);

    if (uniform && fulltile) {
        // 8 packed weight pairs, warp-contiguous SoA loads
        u64 W[8];
#pragma unroll
        for (int a = 0; a < 8; a++) W[a] = g_WpkT[a * NCP + cp];

        const u64* __restrict__ gp = &g_Gdup[ch0 * GPITCH + h0];   // 16B-aligned (h0 even)

        // Ring init: values 0..11
        u64 P[12];
        {
            ulonglong2 t0 = *(const ulonglong2*)(gp);
            ulonglong2 t1 = *(const ulonglong2*)(gp + 2);
            ulonglong2 t2 = *(const ulonglong2*)(gp + 4);
            ulonglong2 t3 = *(const ulonglong2*)(gp + 6);
            ulonglong2 t4 = *(const ulonglong2*)(gp + 8);
            ulonglong2 t5 = *(const ulonglong2*)(gp + 10);
            P[0] = t0.x; P[1] = t0.y; P[2]  = t1.x; P[3]  = t1.y;
            P[4] = t2.x; P[5] = t2.y; P[6]  = t3.x; P[7]  = t3.y;
            P[8] = t4.x; P[9] = t4.y; P[10] = t5.x; P[11] = t5.y;
        }

        char* op = (char*)(out + (size_t)h0 * CTOT + c0);
#pragma unroll
        for (int cyc = 0; cyc < HTILE / 12; cyc++) {
            const int base = cyc * 12;
            PHASE(0); PHASE(1); PHASE(2);
        }
    } else {
        // Slow path: channel-crossing pairs (4 of 2048) and the 13-row tail tile.
        int kk0 = (c0 == CTOT - 1) ? 585 : c0 % 585;
        int kk1 = (c1 == CTOT - 1) ? 585 : c1 % 585;
        float w0[8], w1[8];
#pragma unroll
        for (int a = 0; a < 8; a++) {
            w0[a] = g_Wmid[kk0 * 8 + a];
            w1[a] = g_Wmid[kk1 * 8 + a];
        }
        int hEnd = min(h0 + HTILE, HP);
        for (int h = h0; h < hEnd; h++) {
            const float* ga = (const float*)&g_Gdup[ch0 * GPITCH + h];
            const float* gb = (const float*)&g_Gdup[ch1 * GPITCH + h];
            float s0 = 0.f, s1 = 0.f;
#pragma unroll
            for (int a = 0; a < 8; a++) {
                s0 = fmaf(ga[2 * a], w0[a], s0);
                s1 = fmaf(gb[2 * a], w1[a], s1);
            }
            float2 o; o.x = s0; o.y = s1;
            *(float2*)&out[(size_t)h * CTOT + c0] = o;
        }
    }
}

extern "C" void kernel_launch(void* const* d_in, const int* in_sizes, int n_in,
                              void* d_out, int out_size) {
    const float* x       = (const float*)d_in[0];
    const float* kernels = (const float*)d_in[1];
    if (n_in >= 2 && in_sizes[0] == NK * 24) {   // defensive: swapped order
        kernels = (const float*)d_in[0];
        x       = (const float*)d_in[1];
    }
    float* out = (float*)d_out;

    prep<<<(CIN * GPITCH + 255) / 256, 256>>>(x, kernels);

    dim3 grid(NCP / 256, (HP + HTILE - 1) / HTILE);  // (8, 342) = 2736 CTAs
    conv_main<<<grid, 256>>>(out);
}